// round 1
// baseline (speedup 1.0000x reference)
#include <cuda_runtime.h>
#include <cstdint>

#define HID   2048
#define INTER 10944
#define TMAX  4096
#define EPS   1e-6f

#define BM 128
#define BN 64
#define BK 32
#define PAD 36            // smem row stride in floats: 16B aligned, conflict-free frags
#define NTHREADS 256
#define SMEMSZ ((2*BM*PAD + 2*BN*PAD) * 4)

// ---------------- scratch (static device memory; no allocations) ----------------
__device__ float g_xn[(size_t)TMAX * HID];      // rmsnorm out (xn, then reused as h_post)
__device__ float g_q[(size_t)TMAX * HID];       // q_proj out
__device__ float g_hidden[(size_t)TMAX * HID];  // residual stream after o_proj
__device__ float g_gate[(size_t)TMAX * INTER];  // gate, then silu(gate)*up in place
__device__ float g_up[(size_t)TMAX * INTER];    // up

// ---------------- helpers ----------------
__device__ __forceinline__ float tf32_rna(float f) {
    uint32_t r;
    asm("cvt.rna.tf32.f32 %0, %1;" : "=r"(r) : "f"(f));
    return __uint_as_float(r);
}

__device__ __forceinline__ void cp16(float* smem_dst, const float* gmem_src) {
    uint32_t s = (uint32_t)__cvta_generic_to_shared(smem_dst);
    asm volatile("cp.async.cg.shared.global [%0], [%1], 16;" :: "r"(s), "l"(gmem_src));
}

__device__ __forceinline__ void mma_tf32(float c[4], const uint32_t a[4], const uint32_t b[2]) {
    asm volatile(
        "mma.sync.aligned.m16n8k8.row.col.f32.tf32.tf32.f32 "
        "{%0,%1,%2,%3}, {%4,%5,%6,%7}, {%8,%9}, {%0,%1,%2,%3};"
        : "+f"(c[0]), "+f"(c[1]), "+f"(c[2]), "+f"(c[3])
        : "r"(a[0]), "r"(a[1]), "r"(a[2]), "r"(a[3]), "r"(b[0]), "r"(b[1]));
}

// ---------------- rmsnorm: one block per row, output rounded to tf32 ----------------
__global__ void rmsnorm_kernel(const float* __restrict__ x, const float* __restrict__ w,
                               float* __restrict__ out) {
    const int row = blockIdx.x;
    const int t = threadIdx.x;  // 256 threads, 2048 elems -> 2 float4 per thread
    const float4* xv = reinterpret_cast<const float4*>(x + (size_t)row * HID);
    const float4* wv = reinterpret_cast<const float4*>(w);
    float4* ov = reinterpret_cast<float4*>(out + (size_t)row * HID);

    float4 a = xv[t];
    float4 b = xv[t + 256];
    float ss = a.x*a.x + a.y*a.y + a.z*a.z + a.w*a.w
             + b.x*b.x + b.y*b.y + b.z*b.z + b.w*b.w;

    __shared__ float red[8];
    #pragma unroll
    for (int o = 16; o; o >>= 1) ss += __shfl_xor_sync(0xffffffffu, ss, o);
    if ((t & 31) == 0) red[t >> 5] = ss;
    __syncthreads();
    float tot = red[0] + red[1] + red[2] + red[3] + red[4] + red[5] + red[6] + red[7];
    const float scale = rsqrtf(tot * (1.0f / HID) + EPS);

    float4 wa = wv[t], wb = wv[t + 256];
    float4 o1, o2;
    o1.x = tf32_rna(a.x * scale * wa.x); o1.y = tf32_rna(a.y * scale * wa.y);
    o1.z = tf32_rna(a.z * scale * wa.z); o1.w = tf32_rna(a.w * scale * wa.w);
    o2.x = tf32_rna(b.x * scale * wb.x); o2.y = tf32_rna(b.y * scale * wb.y);
    o2.z = tf32_rna(b.z * scale * wb.z); o2.w = tf32_rna(b.w * scale * wb.w);
    ov[t] = o1;
    ov[t + 256] = o2;
}

// ---------------- silu(gate) * up, in place into gate, rounded to tf32 ----------------
__global__ void silu_mul_kernel(float* __restrict__ gate, const float* __restrict__ up,
                                long long n4) {
    long long i = (long long)blockIdx.x * blockDim.x + threadIdx.x;
    if (i >= n4) return;
    float4 g = reinterpret_cast<float4*>(gate)[i];
    float4 u = reinterpret_cast<const float4*>(up)[i];
    g.x = tf32_rna(g.x / (1.0f + expf(-g.x)) * u.x);
    g.y = tf32_rna(g.y / (1.0f + expf(-g.y)) * u.y);
    g.z = tf32_rna(g.z / (1.0f + expf(-g.z)) * u.z);
    g.w = tf32_rna(g.w / (1.0f + expf(-g.w)) * u.w);
    reinterpret_cast<float4*>(gate)[i] = g;
}

// ---------------- GEMM: C[M,N] = A[M,K] @ B[N,K]^T (+ epilogue) ----------------
// EPI: 0 = plain store, 1 = store rounded to tf32 (feeds next GEMM's A side),
//      2 = store acc + Res[M,N]
template <int EPI>
__global__ __launch_bounds__(NTHREADS)
void gemm_tf32(const float* __restrict__ A, const float* __restrict__ B,
               const float* __restrict__ Res, float* __restrict__ C,
               int M, int N, int K) {
    extern __shared__ float sm[];
    float* As = sm;                    // [2][BM][PAD]
    float* Bs = sm + 2 * BM * PAD;     // [2][BN][PAD]

    const int tid  = threadIdx.x;
    const int bm   = blockIdx.y, bn = blockIdx.x;
    const int lane = tid & 31, warp = tid >> 5;
    const int wm   = warp & 3;   // 4 warps along M
    const int wn   = warp >> 2;  // 2 warps along N
    const int gid  = lane >> 2, tig = lane & 3;

    // cp.async thread mapping: 8 threads per 32-float row (4 floats each)
    const int ar = tid >> 3;          // 0..31
    const int ac = (tid & 7) * 4;
    const float* Ag = A + (size_t)(bm * BM + ar) * K + ac;
    const float* Bg = B + (size_t)(bn * BN + ar) * K + ac;

    const int nkb = K / BK;

    auto issue = [&](int kb, int buf) {
        float* Ad = As + buf * BM * PAD + ar * PAD + ac;
        const float* Asrc = Ag + kb * BK;
        #pragma unroll
        for (int i = 0; i < 4; i++)  // 4 waves of 32 rows -> 128 rows
            cp16(Ad + i * 32 * PAD, Asrc + (size_t)i * 32 * K);
        float* Bd = Bs + buf * BN * PAD + ar * PAD + ac;
        const float* Bsrc = Bg + kb * BK;
        #pragma unroll
        for (int i = 0; i < 2; i++)  // 2 waves of 32 rows -> 64 rows
            cp16(Bd + i * 32 * PAD, Bsrc + (size_t)i * 32 * K);
    };

    float acc[2][4][4];
    #pragma unroll
    for (int mi = 0; mi < 2; mi++)
        #pragma unroll
        for (int ni = 0; ni < 4; ni++)
            #pragma unroll
            for (int r = 0; r < 4; r++) acc[mi][ni][r] = 0.0f;

    issue(0, 0);
    asm volatile("cp.async.commit_group;");

    for (int kb = 0; kb < nkb; ++kb) {
        const int buf = kb & 1;
        if (kb + 1 < nkb) {
            issue(kb + 1, buf ^ 1);
            asm volatile("cp.async.commit_group;");
            asm volatile("cp.async.wait_group 1;");
        } else {
            asm volatile("cp.async.wait_group 0;");
        }
        __syncthreads();

        const float* Ab = As + buf * BM * PAD;
        const float* Bb = Bs + buf * BN * PAD;

        #pragma unroll
        for (int kk = 0; kk < BK / 8; kk++) {
            uint32_t af[2][4];
            #pragma unroll
            for (int mi = 0; mi < 2; mi++) {
                const int r = wm * 32 + mi * 16 + gid;
                const float* p0 = Ab + r * PAD + kk * 8 + tig;
                const float* p1 = p0 + 8 * PAD;
                // A is pre-rounded to tf32 by its producer kernels
                af[mi][0] = __float_as_uint(p0[0]);
                af[mi][2] = __float_as_uint(p0[4]);
                af[mi][1] = __float_as_uint(p1[0]);
                af[mi][3] = __float_as_uint(p1[4]);
            }
            uint32_t bf_[4][2];
            #pragma unroll
            for (int ni = 0; ni < 4; ni++) {
                const float* p = Bb + (wn * 32 + ni * 8 + gid) * PAD + kk * 8 + tig;
                asm("cvt.rna.tf32.f32 %0, %1;" : "=r"(bf_[ni][0]) : "f"(p[0]));
                asm("cvt.rna.tf32.f32 %0, %1;" : "=r"(bf_[ni][1]) : "f"(p[4]));
            }
            #pragma unroll
            for (int mi = 0; mi < 2; mi++)
                #pragma unroll
                for (int ni = 0; ni < 4; ni++)
                    mma_tf32(acc[mi][ni], af[mi], bf_[ni]);
        }
        __syncthreads();
    }

    // epilogue
    const int rbase = bm * BM + wm * 32 + gid;
    const int cbase = bn * BN + wn * 32 + tig * 2;
    #pragma unroll
    for (int mi = 0; mi < 2; mi++) {
        #pragma unroll
        for (int ni = 0; ni < 4; ni++) {
            const int r0 = rbase + mi * 16;
            const int c  = cbase + ni * 8;
            float2 v0 = make_float2(acc[mi][ni][0], acc[mi][ni][1]);
            float2 v1 = make_float2(acc[mi][ni][2], acc[mi][ni][3]);
            if (EPI == 2) {
                float2 r0v = *reinterpret_cast<const float2*>(Res + (size_t)r0 * N + c);
                float2 r1v = *reinterpret_cast<const float2*>(Res + (size_t)(r0 + 8) * N + c);
                v0.x += r0v.x; v0.y += r0v.y;
                v1.x += r1v.x; v1.y += r1v.y;
            }
            if (EPI == 1) {
                v0.x = tf32_rna(v0.x); v0.y = tf32_rna(v0.y);
                v1.x = tf32_rna(v1.x); v1.y = tf32_rna(v1.y);
            }
            *reinterpret_cast<float2*>(C + (size_t)r0 * N + c)       = v0;
            *reinterpret_cast<float2*>(C + (size_t)(r0 + 8) * N + c) = v1;
        }
    }
}

// ---------------- launcher ----------------
extern "C" void kernel_launch(void* const* d_in, const int* in_sizes, int n_in,
                              void* d_out, int out_size) {
    const float* x      = (const float*)d_in[0];
    // d_in[1] = positions (unused by this layer)
    const float* in_w   = (const float*)d_in[2];
    const float* post_w = (const float*)d_in[3];
    const float* Wq     = (const float*)d_in[4];
    const float* Wo     = (const float*)d_in[5];
    const float* Wg     = (const float*)d_in[6];
    const float* Wu     = (const float*)d_in[7];
    const float* Wd     = (const float*)d_in[8];
    float* out = (float*)d_out;

    const int T = in_sizes[0] / HID;   // 4096

    float *xn, *q, *hidden, *gate, *up;
    cudaGetSymbolAddress((void**)&xn,     g_xn);
    cudaGetSymbolAddress((void**)&q,      g_q);
    cudaGetSymbolAddress((void**)&hidden, g_hidden);
    cudaGetSymbolAddress((void**)&gate,   g_gate);
    cudaGetSymbolAddress((void**)&up,     g_up);

    cudaFuncSetAttribute(gemm_tf32<0>, cudaFuncAttributeMaxDynamicSharedMemorySize, SMEMSZ);
    cudaFuncSetAttribute(gemm_tf32<1>, cudaFuncAttributeMaxDynamicSharedMemorySize, SMEMSZ);
    cudaFuncSetAttribute(gemm_tf32<2>, cudaFuncAttributeMaxDynamicSharedMemorySize, SMEMSZ);

    const dim3 gridH(HID / BN,   T / BM);   // N = 2048
    const dim3 gridI(INTER / BN, T / BM);   // N = 10944

    // 1. input_layernorm (rounded to tf32)
    rmsnorm_kernel<<<T, 256>>>(x, in_w, xn);
    // 2. q = xn @ Wq^T (rounded: feeds next GEMM A-side)
    gemm_tf32<1><<<gridH, NTHREADS, SMEMSZ>>>(xn, Wq, nullptr, q, T, HID, HID);
    // 3. hidden = x + q @ Wo^T
    gemm_tf32<2><<<gridH, NTHREADS, SMEMSZ>>>(q, Wo, x, hidden, T, HID, HID);
    // 4. post_attention_layernorm (reuse xn buffer)
    rmsnorm_kernel<<<T, 256>>>(hidden, post_w, xn);
    // 5/6. gate and up projections
    gemm_tf32<0><<<gridI, NTHREADS, SMEMSZ>>>(xn, Wg, nullptr, gate, T, INTER, HID);
    gemm_tf32<0><<<gridI, NTHREADS, SMEMSZ>>>(xn, Wu, nullptr, up,  T, INTER, HID);
    // 7. act = silu(gate) * up, in place into gate
    {
        long long n4 = (long long)T * INTER / 4;
        int blocks = (int)((n4 + 255) / 256);
        silu_mul_kernel<<<blocks, 256>>>(gate, up, n4);
    }
    // 8. out = hidden + act @ Wd^T
    gemm_tf32<2><<<gridH, NTHREADS, SMEMSZ>>>(gate, Wd, hidden, out, T, HID, INTER);
}

// round 3
// speedup vs baseline: 3.6514x; 3.6514x over previous
#include <cuda_runtime.h>
#include <cuda_fp16.h>
#include <cstdint>

#define HID   2048
#define INTER 10944
#define INTP  11008          // padded: 86*128
#define TTOK  4096
#define EPS   1e-6f

#define BM 128
#define BN 128
#define BK 64                // fp16 elems per k-chunk = 128B swizzled row
#define NSTAGE 3
#define A_BYTES (BM*128)     // 16 KB
#define B_BYTES (BN*128)     // 16 KB
#define STAGE_BYTES (A_BYTES + B_BYTES)
#define GEMM_SMEM (NSTAGE*STAGE_BYTES)

// ---------------- scratch (static device memory) ----------------
__device__ __half g_xn[(size_t)TTOK * HID];
__device__ __half g_q[(size_t)TTOK * HID];
__device__ float  g_hidden[(size_t)TTOK * HID];
__device__ __half g_gate[(size_t)TTOK * INTP];
__device__ __half g_up[(size_t)TTOK * INTP];
__device__ __half g_wq[(size_t)HID * HID];
__device__ __half g_wo[(size_t)HID * HID];
__device__ __half g_wg[(size_t)INTP * HID];
__device__ __half g_wu[(size_t)INTP * HID];
__device__ __half g_wd[(size_t)HID * INTP];

// ---------------- PTX helpers ----------------
__device__ __forceinline__ uint32_t smem_u32(const void* p) {
    uint32_t a;
    asm("{ .reg .u64 t; cvta.to.shared.u64 t, %1; cvt.u32.u64 %0, t; }" : "=r"(a) : "l"(p));
    return a;
}
#define SWZ(off) ((off) ^ (((off) >> 3) & 0x70))

__device__ __forceinline__ void cp16(uint32_t smem_dst, const void* gsrc) {
    asm volatile("cp.async.cg.shared.global [%0], [%1], 16;" :: "r"(smem_dst), "l"(gsrc));
}
#define CP_COMMIT  asm volatile("cp.async.commit_group;" ::: "memory")
#define CP_WAIT(n) asm volatile("cp.async.wait_group %0;" :: "n"(n) : "memory")

__device__ __forceinline__ void ldsm_x4(uint32_t r[4], uint32_t saddr) {
    asm volatile("ldmatrix.sync.aligned.m8n8.x4.shared.b16 {%0,%1,%2,%3}, [%4];"
        : "=r"(r[0]), "=r"(r[1]), "=r"(r[2]), "=r"(r[3]) : "r"(saddr));
}

__device__ __forceinline__ void mma16816(float c[4], const uint32_t a[4],
                                         uint32_t b0, uint32_t b1) {
    asm volatile(
        "mma.sync.aligned.m16n8k16.row.col.f32.f16.f16.f32 "
        "{%0,%1,%2,%3}, {%4,%5,%6,%7}, {%8,%9}, {%0,%1,%2,%3};"
        : "+f"(c[0]), "+f"(c[1]), "+f"(c[2]), "+f"(c[3])
        : "r"(a[0]), "r"(a[1]), "r"(a[2]), "r"(a[3]), "r"(b0), "r"(b1));
}

// ---------------- fp16 mma GEMM:  C[M,N] = A[M,K] @ B[N,K]^T ----------------
// EPI 0: store fp16 to Ch.   EPI 1: store fp32 (acc + Res) to Cf.
template <int EPI>
__global__ void __launch_bounds__(256, 2)
gemm_h(const __half* __restrict__ A, const __half* __restrict__ B,
       const float* __restrict__ Res, __half* __restrict__ Ch,
       float* __restrict__ Cf, int K, int N) {
    extern __shared__ char smem[];
    const uint32_t sb = smem_u32(smem);
    const int tid = threadIdx.x, warp = tid >> 5, lane = tid & 31;
    const int wm = warp & 1, wn = warp >> 1;          // 2 x 4 warp grid
    const int m0 = blockIdx.x * BM, n0 = blockIdx.y * BN;
    const int nkb = K / BK;

    // ---- loader mapping: 2048 16B chunks/stage, 8 per thread ----
    const __half* Ag = A + (size_t)m0 * K;
    const __half* Bg = B + (size_t)n0 * K;
    auto issue = [&](int kb) {
        const uint32_t base = sb + (kb % NSTAGE) * STAGE_BYTES;
        const int koff = kb * BK;
        #pragma unroll
        for (int i = 0; i < 8; i++) {
            const int c = tid + i * 256;
            const int r = (c & 1023) >> 3, cc = c & 7;
            const uint32_t so = SWZ((uint32_t)(r * 128 + cc * 16));
            if (c < 1024) cp16(base + so,          Ag + (size_t)r * K + koff + cc * 8);
            else          cp16(base + A_BYTES + so, Bg + (size_t)r * K + koff + cc * 8);
        }
    };

    // ---- per-thread ldmatrix lane address components ----
    const int frow = (lane & 7) | (((lane >> 3) & 1) << 3);  // 0..15
    const int fg   = lane >> 4;                              // 0..1
    const int fx   = frow & 7;
    uint32_t arow[4], brow[2];
    #pragma unroll
    for (int mi = 0; mi < 4; mi++) arow[mi] = (uint32_t)((wm * 64 + mi * 16 + frow) * 128);
    #pragma unroll
    for (int nj = 0; nj < 2; nj++) brow[nj] = (uint32_t)(A_BYTES + (wn * 32 + nj * 16 + frow) * 128);

    float acc[4][4][4];
    #pragma unroll
    for (int mi = 0; mi < 4; mi++)
        #pragma unroll
        for (int j = 0; j < 4; j++)
            #pragma unroll
            for (int r = 0; r < 4; r++) acc[mi][j][r] = 0.0f;

    issue(0); CP_COMMIT;
    issue(1); CP_COMMIT;

    for (int kb = 0; kb < nkb; ++kb) {
        if (kb + 2 < nkb)      { issue(kb + 2); CP_COMMIT; CP_WAIT(2); }
        else if (kb + 1 < nkb) { CP_WAIT(1); }
        else                   { CP_WAIT(0); }
        __syncthreads();

        const uint32_t base = sb + (kb % NSTAGE) * STAGE_BYTES;
        #pragma unroll
        for (int ks = 0; ks < 4; ks++) {
            const uint32_t colx = (uint32_t)(((2 * ks + fg) ^ fx) << 4);
            uint32_t a[4][4];
            #pragma unroll
            for (int mi = 0; mi < 4; mi++) ldsm_x4(a[mi], base + arow[mi] + colx);
            uint32_t b[2][4];
            #pragma unroll
            for (int nj = 0; nj < 2; nj++) ldsm_x4(b[nj], base + brow[nj] + colx);
            #pragma unroll
            for (int mi = 0; mi < 4; mi++) {
                #pragma unroll
                for (int nj = 0; nj < 2; nj++) {
                    mma16816(acc[mi][2 * nj + 0], a[mi], b[nj][0], b[nj][2]);
                    mma16816(acc[mi][2 * nj + 1], a[mi], b[nj][1], b[nj][3]);
                }
            }
        }
        __syncthreads();
    }

    // ---- epilogue ----
    const int rb = m0 + wm * 64 + (lane >> 2);
    const int cb = n0 + wn * 32 + (lane & 3) * 2;
    #pragma unroll
    for (int mi = 0; mi < 4; mi++) {
        #pragma unroll
        for (int j = 0; j < 4; j++) {
            const int r0 = rb + mi * 16;
            const int c  = cb + j * 8;
            if (EPI == 0) {
                *(__half2*)(Ch + (size_t)r0 * N + c) =
                    __floats2half2_rn(acc[mi][j][0], acc[mi][j][1]);
                *(__half2*)(Ch + (size_t)(r0 + 8) * N + c) =
                    __floats2half2_rn(acc[mi][j][2], acc[mi][j][3]);
            } else {
                float2 v0 = *(const float2*)(Res + (size_t)r0 * N + c);
                float2 v1 = *(const float2*)(Res + (size_t)(r0 + 8) * N + c);
                v0.x += acc[mi][j][0]; v0.y += acc[mi][j][1];
                v1.x += acc[mi][j][2]; v1.y += acc[mi][j][3];
                *(float2*)(Cf + (size_t)r0 * N + c)       = v0;
                *(float2*)(Cf + (size_t)(r0 + 8) * N + c) = v1;
            }
        }
    }
}

// ---------------- fp32 -> fp16 weight convert with padding ----------------
__global__ void cvt_pad(const float* __restrict__ in, __half* __restrict__ out,
                        int ro, int co, int ri, int ci) {
    const size_t i = (size_t)blockIdx.x * blockDim.x + threadIdx.x;
    const size_t n4 = ((size_t)ro * co) >> 2;
    if (i >= n4) return;
    const int cw = co >> 2;
    const int r = (int)(i / cw);
    const int c = (int)(i - (size_t)r * cw) * 4;
    __half2 h0 = __floats2half2_rn(0.f, 0.f), h1 = h0;
    if (r < ri && c < ci) {
        float4 v = *(const float4*)(in + (size_t)r * ci + c);
        h0 = __floats2half2_rn(v.x, v.y);
        h1 = __floats2half2_rn(v.z, v.w);
    }
    __half2* d = (__half2*)(out + (size_t)r * co + c);
    d[0] = h0; d[1] = h1;
}

// ---------------- rmsnorm -> fp16 ----------------
__global__ void rmsnorm_h(const float* __restrict__ x, const float* __restrict__ w,
                          __half* __restrict__ out) {
    const int row = blockIdx.x, t = threadIdx.x;
    const float4* xv = (const float4*)(x + (size_t)row * HID);
    const float4* wv = (const float4*)w;
    float4 a = xv[t], b = xv[t + 256];
    float ss = a.x*a.x + a.y*a.y + a.z*a.z + a.w*a.w
             + b.x*b.x + b.y*b.y + b.z*b.z + b.w*b.w;
    __shared__ float red[8];
    #pragma unroll
    for (int o = 16; o; o >>= 1) ss += __shfl_xor_sync(0xffffffffu, ss, o);
    if ((t & 31) == 0) red[t >> 5] = ss;
    __syncthreads();
    float tot = red[0]+red[1]+red[2]+red[3]+red[4]+red[5]+red[6]+red[7];
    const float sc = rsqrtf(tot * (1.0f / HID) + EPS);
    float4 wa = wv[t], wb = wv[t + 256];
    __half2* ov = (__half2*)(out + (size_t)row * HID);
    ov[2*t]   = __floats2half2_rn(a.x*sc*wa.x, a.y*sc*wa.y);
    ov[2*t+1] = __floats2half2_rn(a.z*sc*wa.z, a.w*sc*wa.w);
    ov[2*(t+256)]   = __floats2half2_rn(b.x*sc*wb.x, b.y*sc*wb.y);
    ov[2*(t+256)+1] = __floats2half2_rn(b.z*sc*wb.z, b.w*sc*wb.w);
}

// ---------------- silu(gate)*up (fp16 in/out, fp32 math) ----------------
__global__ void silu_h(__half* __restrict__ gate, const __half* __restrict__ up,
                       long long n8) {
    const long long i = (long long)blockIdx.x * blockDim.x + threadIdx.x;
    if (i >= n8) return;
    uint4 gv = ((const uint4*)gate)[i];
    uint4 uv = ((const uint4*)up)[i];
    uint32_t* gp = (uint32_t*)&gv;
    uint32_t* upp = (uint32_t*)&uv;
    #pragma unroll
    for (int j = 0; j < 4; j++) {
        float2 g = __half22float2(*(__half2*)&gp[j]);
        float2 u = __half22float2(*(__half2*)&upp[j]);
        g.x = g.x / (1.0f + expf(-g.x)) * u.x;
        g.y = g.y / (1.0f + expf(-g.y)) * u.y;
        *(__half2*)&gp[j] = __float22half2_rn(g);
    }
    ((uint4*)gate)[i] = gv;
}

// ---------------- launcher ----------------
extern "C" void kernel_launch(void* const* d_in, const int* in_sizes, int n_in,
                              void* d_out, int out_size) {
    const float* x      = (const float*)d_in[0];
    const float* in_w   = (const float*)d_in[2];
    const float* post_w = (const float*)d_in[3];
    const float* Wq     = (const float*)d_in[4];
    const float* Wo     = (const float*)d_in[5];
    const float* Wg     = (const float*)d_in[6];
    const float* Wu     = (const float*)d_in[7];
    const float* Wd     = (const float*)d_in[8];
    float* out = (float*)d_out;
    const int T = in_sizes[0] / HID;  // 4096

    __half *xn, *q, *gate, *up, *wq, *wo, *wg, *wu, *wd;
    float* hidden;
    cudaGetSymbolAddress((void**)&xn, g_xn);
    cudaGetSymbolAddress((void**)&q, g_q);
    cudaGetSymbolAddress((void**)&hidden, g_hidden);
    cudaGetSymbolAddress((void**)&gate, g_gate);
    cudaGetSymbolAddress((void**)&up, g_up);
    cudaGetSymbolAddress((void**)&wq, g_wq);
    cudaGetSymbolAddress((void**)&wo, g_wo);
    cudaGetSymbolAddress((void**)&wg, g_wg);
    cudaGetSymbolAddress((void**)&wu, g_wu);
    cudaGetSymbolAddress((void**)&wd, g_wd);

    cudaFuncSetAttribute(gemm_h<0>, cudaFuncAttributeMaxDynamicSharedMemorySize, GEMM_SMEM);
    cudaFuncSetAttribute(gemm_h<1>, cudaFuncAttributeMaxDynamicSharedMemorySize, GEMM_SMEM);

    // weight conversion (fp32 -> fp16, padded for INTER)
    {
        auto launch_cvt = [&](const float* src, __half* dst, int ro, int co, int ri, int ci) {
            size_t n4 = ((size_t)ro * co) >> 2;
            cvt_pad<<<(unsigned)((n4 + 255) / 256), 256>>>(src, dst, ro, co, ri, ci);
        };
        launch_cvt(Wq, wq, HID, HID, HID, HID);
        launch_cvt(Wo, wo, HID, HID, HID, HID);
        launch_cvt(Wg, wg, INTP, HID, INTER, HID);
        launch_cvt(Wu, wu, INTP, HID, INTER, HID);
        launch_cvt(Wd, wd, HID, INTP, HID, INTER);
    }

    const dim3 gridH(T / BM, HID / BN);    // (32, 16)
    const dim3 gridI(T / BM, INTP / BN);   // (32, 86)

    // 1. input_layernorm -> fp16
    rmsnorm_h<<<T, 256>>>(x, in_w, xn);
    // 2. q = xn @ Wq^T (fp16 out)
    gemm_h<0><<<gridH, 256, GEMM_SMEM>>>(xn, wq, nullptr, q, nullptr, HID, HID);
    // 3. hidden = x + q @ Wo^T (fp32 out)
    gemm_h<1><<<gridH, 256, GEMM_SMEM>>>(q, wo, x, nullptr, hidden, HID, HID);
    // 4. post_attention_layernorm -> fp16
    rmsnorm_h<<<T, 256>>>(hidden, post_w, xn);
    // 5/6. gate & up projections (fp16 out, padded N)
    gemm_h<0><<<gridI, 256, GEMM_SMEM>>>(xn, wg, nullptr, gate, nullptr, HID, INTP);
    gemm_h<0><<<gridI, 256, GEMM_SMEM>>>(xn, wu, nullptr, up, nullptr, HID, INTP);
    // 7. act = silu(gate)*up in place
    {
        long long n8 = (long long)T * INTP / 8;
        silu_h<<<(unsigned)((n8 + 255) / 256), 256>>>(gate, up, n8);
    }
    // 8. out = hidden + act @ Wd^T (fp32 out)
    gemm_h<1><<<gridH, 256, GEMM_SMEM>>>(gate, wd, hidden, nullptr, out, INTP, HID);
}